// round 10
// baseline (speedup 1.0000x reference)
#include <cuda_runtime.h>
#include <cstdint>

typedef unsigned long long ull;

__device__ __forceinline__ ull pack2(float x) {
    ull r; asm("mov.b64 %0, {%1, %1};" : "=l"(r) : "f"(x)); return r;
}
__device__ __forceinline__ void ffma2(ull &d, ull a, ull b) {
    asm("fma.rn.f32x2 %0, %1, %2, %0;" : "+l"(d) : "l"(a), "l"(b));
}
__device__ __forceinline__ void unpack2(ull v, float &lo, float &hi) {
    asm("mov.b64 {%0, %1}, %2;" : "=f"(lo), "=f"(hi) : "l"(v));
}
__device__ __forceinline__ uint32_t smem_u32(const void* p) {
    uint32_t a;
    asm("{ .reg .u64 t; cvta.to.shared.u64 t, %1; cvt.u32.u64 %0, t; }"
        : "=r"(a) : "l"(p));
    return a;
}

// ---- bulk-copy + mbarrier primitives ----
#define CP_BULK(dst, src, bytes, mbar) \
    asm volatile("cp.async.bulk.shared::cta.global.mbarrier::complete_tx::bytes " \
                 "[%0], [%1], %2, [%3];" \
                 :: "r"(dst), "l"(src), "r"(bytes), "r"(mbar) : "memory")
#define MBAR_INIT(mbar, cnt) \
    asm volatile("mbarrier.init.shared.b64 [%0], %1;" :: "r"(mbar), "r"(cnt) : "memory")
#define MBAR_EXPECT_TX(mbar, bytes) \
    asm volatile("mbarrier.arrive.expect_tx.shared.b64 _, [%0], %1;" \
                 :: "r"(mbar), "r"(bytes) : "memory")
__device__ __forceinline__ void mbar_wait(uint32_t mbar, uint32_t parity) {
    asm volatile(
        "{\n\t"
        ".reg .pred P;\n\t"
        "WAIT_%=:\n\t"
        "mbarrier.try_wait.parity.acquire.cta.shared::cta.b64 P, [%0], %1, 0x989680;\n\t"
        "@P bra.uni DONE_%=;\n\t"
        "bra.uni WAIT_%=;\n\t"
        "DONE_%=:\n\t"
        "}"
        :: "r"(mbar), "r"(parity) : "memory");
}

// Chunk = 8 u's. Per-node per-chunk row: [x0 8][x1 24][pad 4] = 36 floats (144B)
#define ROWF 36
#define BUFF (32 * ROWF)               // one buffer: 32 nodes = 1152 floats
#define NBUF 4
#define XRW  (NBUF * BUFF)             // 4608 floats per warp
#define WSH  8192                      // weights: 4 x 2048 floats (scaled)
#define MBW  8                         // mbar region per warp: 4 barriers x 8B (floats)
#define SMEM_FLOATS (WSH + 4 * XRW + 4 * MBW)   // 8192+18432+32 = 26656
#define SMEM_BYTES  (SMEM_FLOATS * 4)           // 106624 (x2 CTAs = 213 KB)
#define CHUNK_BYTES 4096u               // 32 nodes x 128B per chunk

// Stage chunk c for this warp's 32 nodes: lane l bulk-copies its own node's
// contiguous slices (x0: 32B @ 32c, x1: 96B @ 512+96c). 2 bulk ops per lane.
__device__ __forceinline__ void stage_bulk(
    uint32_t xr, const float* __restrict__ nfwarp, int c, int lane, uint32_t mbar)
{
    if (lane == 0) MBAR_EXPECT_TX(mbar, CHUNK_BYTES);
    const float* nsrc = nfwarp + (size_t)lane * 512;
    uint32_t dst = xr + (uint32_t)(lane * ROWF) * 4u;
    CP_BULK(dst,       nsrc + 8*c,        32u, mbar);
    CP_BULK(dst + 32u, nsrc + 128 + 24*c, 96u, mbar);
}

__global__ void __launch_bounds__(128, 2) fctp_main(
    const float* __restrict__ nf, const float* __restrict__ pf,
    const float* __restrict__ w000, const float* __restrict__ w011,
    const float* __restrict__ w101, const float* __restrict__ w110,
    float* __restrict__ out)
{
    extern __shared__ float S[];
    float* Wm = S;
    const int tid  = threadIdx.x;
    const int warp = tid >> 5, lane = tid & 31;

    // Weights scaled by 0.01*C; per u: [w000 16][w011 16][w110 16][w101 16]
    {
        const float c000 = 3.125e-4f;                // 0.01/32
        const float c110 = 1.8042195912175807e-4f;   // 0.01/(32*sqrt(3))
        for (int i = tid; i < 2048; i += 128) {
            int u = i >> 4, j = i & 15;
            Wm[u*64 +      j] = c000 * w000[i];
            Wm[u*64 + 16 + j] = c000 * w011[i];
            Wm[u*64 + 32 + j] = c110 * w110[i];
            Wm[u*64 + 48 + j] = c000 * w101[i];
        }
    }

    // Per-warp mbarrier ring (4 barriers)
    const uint32_t mb0 = smem_u32(S + WSH + 4*XRW) + (uint32_t)warp * 32u;
    if (lane == 0) {
        MBAR_INIT(mb0,       1);
        MBAR_INIT(mb0 + 8u,  1);
        MBAR_INIT(mb0 + 16u, 1);
        MBAR_INIT(mb0 + 24u, 1);
    }
    __syncthreads();   // weights + mbarrier init visible

    float* XR = S + WSH + warp * XRW;
    const uint32_t xrb = smem_u32(XR);
    const int nodeBase = blockIdx.x * 128 + warp * 32;
    const float* nfwarp = nf + (size_t)nodeBase * 512;

    // Accumulators: (v*4+w) col pairs. 64 ull = 128 fp32.
    ull z000[8], z011[8], z110[3][8], z101[3][8];
    #pragma unroll
    for (int p = 0; p < 8; p++) {
        z000[p] = 0ull; z011[p] = 0ull;
        z110[0][p] = 0ull; z110[1][p] = 0ull; z110[2][p] = 0ull;
        z101[0][p] = 0ull; z101[1][p] = 0ull; z101[2][p] = 0ull;
    }

    // depth-3 prologue
    stage_bulk(xrb,                nfwarp, 0, lane, mb0);
    stage_bulk(xrb + BUFF*4u,      nfwarp, 1, lane, mb0 + 8u);
    stage_bulk(xrb + 2u*BUFF*4u,   nfwarp, 2, lane, mb0 + 16u);

    for (int c = 0; c < 16; c++) {                    // 16 chunks of 8 u's
        if (c < 13) {
            int b = (c + 3) & 3;
            stage_bulk(xrb + (uint32_t)(b * BUFF) * 4u,
                       nfwarp, c + 3, lane, mb0 + (uint32_t)b * 8u);
        }
        // wait for chunk c: buffer c&3, completion #(c>>2) -> parity (c>>2)&1
        mbar_wait(mb0 + (uint32_t)((c & 3) * 8), (uint32_t)((c >> 2) & 1));

        const float* myrow = XR + (c & 3) * BUFF + lane * ROWF;
        #pragma unroll
        for (int g = 0; g < 2; g++) {                 // 2 groups of 4 u's
            float4 q0 = *reinterpret_cast<const float4*>(myrow + 4*g);
            float4 qa = *reinterpret_cast<const float4*>(myrow + 8 + 12*g);
            float4 qb = *reinterpret_cast<const float4*>(myrow + 8 + 12*g + 4);
            float4 qc = *reinterpret_cast<const float4*>(myrow + 8 + 12*g + 8);
            float x0s[4] = { q0.x, q0.y, q0.z, q0.w };
            float f1[12] = { qa.x, qa.y, qa.z, qa.w,
                             qb.x, qb.y, qb.z, qb.w,
                             qc.x, qc.y, qc.z, qc.w };
            #pragma unroll
            for (int j = 0; j < 4; j++) {
                const int u = 8*c + 4*g + j;
                const ulonglong2* wp =
                    reinterpret_cast<const ulonglong2*>(Wm + u * 64);
                ull xa  = pack2(x0s[j]);
                ull xb0 = pack2(f1[3*j + 0]);
                ull xb1 = pack2(f1[3*j + 1]);
                ull xb2 = pack2(f1[3*j + 2]);
                #pragma unroll
                for (int p = 0; p < 4; p++) {         // w000 (x0)
                    ulonglong2 w = wp[p];
                    ffma2(z000[2*p],   xa, w.x);
                    ffma2(z000[2*p+1], xa, w.y);
                }
                #pragma unroll
                for (int p = 0; p < 4; p++) {         // w011 (x0)
                    ulonglong2 w = wp[4 + p];
                    ffma2(z011[2*p],   xa, w.x);
                    ffma2(z011[2*p+1], xa, w.y);
                }
                #pragma unroll
                for (int p = 0; p < 4; p++) {         // w110 (x1[.,i])
                    ulonglong2 w = wp[8 + p];
                    ffma2(z110[0][2*p],   xb0, w.x);
                    ffma2(z110[0][2*p+1], xb0, w.y);
                    ffma2(z110[1][2*p],   xb1, w.x);
                    ffma2(z110[1][2*p+1], xb1, w.y);
                    ffma2(z110[2][2*p],   xb2, w.x);
                    ffma2(z110[2][2*p+1], xb2, w.y);
                }
                #pragma unroll
                for (int p = 0; p < 4; p++) {         // w101 (x1[.,k])
                    ulonglong2 w = wp[12 + p];
                    ffma2(z101[0][2*p],   xb0, w.x);
                    ffma2(z101[0][2*p+1], xb0, w.y);
                    ffma2(z101[1][2*p],   xb1, w.x);
                    ffma2(z101[1][2*p+1], xb1, w.y);
                    ffma2(z101[2][2*p],   xb2, w.x);
                    ffma2(z101[2][2*p+1], xb2, w.y);
                }
            }
        }
        __syncwarp();   // all lanes done reading buffer before it is restaged
    }

    // ---------------- epilogue (registers only) ----------------
    const int node = nodeBase + lane;

    float f000[16], f011[16], f110[3][16], f101[3][16];
    #pragma unroll
    for (int p = 0; p < 8; p++) {
        unpack2(z000[p], f000[2*p], f000[2*p+1]);
        unpack2(z011[p], f011[2*p], f011[2*p+1]);
        #pragma unroll
        for (int i = 0; i < 3; i++) {
            unpack2(z110[i][p], f110[i][2*p], f110[i][2*p+1]);
            unpack2(z101[i][p], f101[i][2*p], f101[i][2*p+1]);
        }
    }

    float y[16];
    {
        const float4* p4 = reinterpret_cast<const float4*>(pf + (size_t)node * 16);
        #pragma unroll
        for (int q = 0; q < 4; q++) {
            float4 t = p4[q];
            y[4*q+0] = t.x; y[4*q+1] = t.y; y[4*q+2] = t.z; y[4*q+3] = t.w;
        }
    }

    float o0[4], o1[4][3];
    #pragma unroll
    for (int w = 0; w < 4; w++) {
        float s = 0.f, t = 0.f;
        #pragma unroll
        for (int v = 0; v < 4; v++) {
            s += f000[v*4 + w] * y[v];
            #pragma unroll
            for (int i = 0; i < 3; i++)
                t += f110[i][v*4 + w] * y[4 + 3*v + i];
        }
        o0[w] = s + t;
    }
    #pragma unroll
    for (int w = 0; w < 4; w++) {
        #pragma unroll
        for (int k = 0; k < 3; k++) {
            float s = 0.f, t = 0.f;
            #pragma unroll
            for (int v = 0; v < 4; v++) {
                s += f011[v*4 + w]    * y[4 + 3*v + k];
                t += f101[k][v*4 + w] * y[v];
            }
            o1[w][k] = s + t;
        }
    }
    o0[0] = 0.0f;   // reference zeroes out[:,0]

    float4* o4 = reinterpret_cast<float4*>(out + (size_t)node * 16);
    o4[0] = make_float4(o0[0],    o0[1],    o0[2],    o0[3]);
    o4[1] = make_float4(o1[0][0], o1[0][1], o1[0][2], o1[1][0]);
    o4[2] = make_float4(o1[1][1], o1[1][2], o1[2][0], o1[2][1]);
    o4[3] = make_float4(o1[2][2], o1[3][0], o1[3][1], o1[3][2]);
}

// naive tail kernel (only runs if n % 128 != 0; negligible work)
__global__ void fctp_tail(
    const float* __restrict__ nf, const float* __restrict__ pf,
    const float* __restrict__ w000, const float* __restrict__ w011,
    const float* __restrict__ w101, const float* __restrict__ w110,
    float* __restrict__ out, int start, int n)
{
    int node = start + blockIdx.x * blockDim.x + threadIdx.x;
    if (node >= n) return;
    const float* x = nf + (size_t)node * 512;
    const float* y = pf + (size_t)node * 16;
    float y0v[4], y1v[4][3];
    for (int v0 = 0; v0 < 4; v0++) {
        y0v[v0] = y[v0];
        for (int i = 0; i < 3; i++) y1v[v0][i] = y[4 + 3*v0 + i];
    }
    float o0[4] = {0,0,0,0}, o1[4][3] = {};
    for (int u = 0; u < 128; u++) {
        float x0u = x[u];
        float x1u[3] = { x[128 + 3*u], x[128 + 3*u + 1], x[128 + 3*u + 2] };
        for (int v0 = 0; v0 < 4; v0++) {
            float s110 = x1u[0]*y1v[v0][0] + x1u[1]*y1v[v0][1] + x1u[2]*y1v[v0][2];
            float xy0 = x0u * y0v[v0];
            for (int w = 0; w < 4; w++) {
                int idx = u*16 + v0*4 + w;
                o0[w] += 3.125e-4f * xy0 * w000[idx]
                       + 1.8042195912175807e-4f * s110 * w110[idx];
                for (int k = 0; k < 3; k++)
                    o1[w][k] += 3.125e-4f * (x0u * y1v[v0][k] * w011[idx]
                                           + x1u[k] * y0v[v0] * w101[idx]);
            }
        }
    }
    o0[0] = 0.0f;
    float* op = out + (size_t)node * 16;
    for (int w = 0; w < 4; w++) op[w] = o0[w];
    for (int w = 0; w < 4; w++)
        for (int k = 0; k < 3; k++) op[4 + 3*w + k] = o1[w][k];
}

extern "C" void kernel_launch(void* const* d_in, const int* in_sizes, int n_in,
                              void* d_out, int out_size) {
    const float* nf   = (const float*)d_in[0];
    const float* pf   = (const float*)d_in[1];
    const float* w000 = (const float*)d_in[2];
    const float* w011 = (const float*)d_in[3];
    const float* w101 = (const float*)d_in[4];
    const float* w110 = (const float*)d_in[5];
    float* out = (float*)d_out;
    int n = in_sizes[0] / 512;
    int nb  = n >> 7;
    int rem = n & 127;
    cudaFuncSetAttribute(fctp_main, cudaFuncAttributeMaxDynamicSharedMemorySize, SMEM_BYTES);
    if (nb > 0)
        fctp_main<<<nb, 128, SMEM_BYTES>>>(nf, pf, w000, w011, w101, w110, out);
    if (rem > 0)
        fctp_tail<<<1, 128>>>(nf, pf, w000, w011, w101, w110, out, nb * 128, n);
}

// round 11
// speedup vs baseline: 1.9244x; 1.9244x over previous
#include <cuda_runtime.h>
#include <cstdint>

typedef unsigned long long ull;

__device__ __forceinline__ ull pack2(float x) {
    ull r; asm("mov.b64 %0, {%1, %1};" : "=l"(r) : "f"(x)); return r;
}
__device__ __forceinline__ void ffma2(ull &d, ull a, ull b) {
    asm("fma.rn.f32x2 %0, %1, %2, %0;" : "+l"(d) : "l"(a), "l"(b));
}
__device__ __forceinline__ void unpack2(ull v, float &lo, float &hi) {
    asm("mov.b64 {%0, %1}, %2;" : "=f"(lo), "=f"(hi) : "l"(v));
}
__device__ __forceinline__ uint32_t smem_u32(const void* p) {
    uint32_t a;
    asm("{ .reg .u64 t; cvta.to.shared.u64 t, %1; cvt.u32.u64 %0, t; }"
        : "=r"(a) : "l"(p));
    return a;
}
#define CP_ASYNC16(dst, src) \
    asm volatile("cp.async.cg.shared.global [%0], [%1], 16;" :: "r"(dst), "l"(src))
#define CP_COMMIT()  asm volatile("cp.async.commit_group;" ::: "memory")
#define CP_WAIT(N)   asm volatile("cp.async.wait_group %0;" :: "n"(N) : "memory")

// Chunk = 8 u's. Per-node per-chunk row: [x0 8][x1 24][pad 4] = 36 floats (144B)
#define ROWF 36
#define BUFF (32 * ROWF)               // one buffer: 32 nodes = 1152 floats
#define NBUF 4
#define XRW  (NBUF * BUFF)             // 4608 floats per warp
#define WSH  8192                      // weights: 4 x 2048 floats (scaled)
#define SMEM_FLOATS (WSH + 4 * XRW)    // 8192 + 18432 = 26624
#define SMEM_BYTES  (SMEM_FLOATS * 4)  // 106496 (x2 CTAs = 213 KB <= 228 KB)

// Stage chunk c (8 u's) for this warp's 32 nodes (R8 geometry:
// each instruction covers 4 nodes' contiguous 16B pieces -> few lines/instr).
__device__ __forceinline__ void stage_chunk(
    uint32_t xr, const float* __restrict__ nfwarp, int c, int lane)
{
    const int node_lo = lane >> 3, piece = lane & 7;
    const int so  = (piece < 2) ? (8*c + 4*piece) : (128 + 24*c + 4*(piece - 2));
    const int doo = (piece < 2) ? (4*piece)       : (8 + 4*(piece - 2));
    #pragma unroll
    for (int i = 0; i < 8; i++) {
        int node = node_lo * 8 + i;
        CP_ASYNC16(xr + (uint32_t)(node * ROWF + doo) * 4u,
                   nfwarp + (size_t)node * 512 + so);
    }
}

__global__ void __launch_bounds__(128, 2) fctp_main(
    const float* __restrict__ nf, const float* __restrict__ pf,
    const float* __restrict__ w000, const float* __restrict__ w011,
    const float* __restrict__ w101, const float* __restrict__ w110,
    float* __restrict__ out)
{
    extern __shared__ float S[];
    float* Wm = S;
    const int tid  = threadIdx.x;
    const int warp = tid >> 5, lane = tid & 31;

    // Weights scaled by 0.01*C; per u: [w000 16][w011 16][w110 16][w101 16]
    {
        const float c000 = 3.125e-4f;                // 0.01/32
        const float c110 = 1.8042195912175807e-4f;   // 0.01/(32*sqrt(3))
        for (int i = tid; i < 2048; i += 128) {
            int u = i >> 4, j = i & 15;
            Wm[u*64 +      j] = c000 * w000[i];
            Wm[u*64 + 16 + j] = c000 * w011[i];
            Wm[u*64 + 32 + j] = c110 * w110[i];
            Wm[u*64 + 48 + j] = c000 * w101[i];
        }
    }
    __syncthreads();

    float* XR = S + WSH + warp * XRW;
    const uint32_t xrb = smem_u32(XR);
    const int nodeBase = blockIdx.x * 128 + warp * 32;
    const float* nfwarp = nf + (size_t)nodeBase * 512;

    // Accumulators: (v*4+w) col pairs. 64 ull = 128 fp32.
    ull z000[8], z011[8], z110[3][8], z101[3][8];
    #pragma unroll
    for (int p = 0; p < 8; p++) {
        z000[p] = 0ull; z011[p] = 0ull;
        z110[0][p] = 0ull; z110[1][p] = 0ull; z110[2][p] = 0ull;
        z101[0][p] = 0ull; z101[1][p] = 0ull; z101[2][p] = 0ull;
    }

    // depth-3 prologue
    stage_chunk(xrb,              nfwarp, 0, lane);  CP_COMMIT();
    stage_chunk(xrb + BUFF*4u,    nfwarp, 1, lane);  CP_COMMIT();
    stage_chunk(xrb + 2u*BUFF*4u, nfwarp, 2, lane);  CP_COMMIT();

    for (int c = 0; c < 16; c++) {                    // 16 chunks of 8 u's
        if (c < 13) {
            stage_chunk(xrb + (uint32_t)(((c + 3) & 3) * BUFF) * 4u,
                        nfwarp, c + 3, lane);
            CP_COMMIT();
            CP_WAIT(3);                               // chunk c's group done
        } else if (c == 13) {
            CP_WAIT(2);
        } else if (c == 14) {
            CP_WAIT(1);
        } else {
            CP_WAIT(0);
        }
        __syncwarp();

        const float* myrow = XR + (c & 3) * BUFF + lane * ROWF;
        #pragma unroll
        for (int g = 0; g < 2; g++) {                 // 2 groups of 4 u's
            float4 q0 = *reinterpret_cast<const float4*>(myrow + 4*g);
            float4 qa = *reinterpret_cast<const float4*>(myrow + 8 + 12*g);
            float4 qb = *reinterpret_cast<const float4*>(myrow + 8 + 12*g + 4);
            float4 qc = *reinterpret_cast<const float4*>(myrow + 8 + 12*g + 8);
            float x0s[4] = { q0.x, q0.y, q0.z, q0.w };
            float f1[12] = { qa.x, qa.y, qa.z, qa.w,
                             qb.x, qb.y, qb.z, qb.w,
                             qc.x, qc.y, qc.z, qc.w };
            #pragma unroll
            for (int j = 0; j < 4; j++) {
                const int u = 8*c + 4*g + j;
                const ulonglong2* wp =
                    reinterpret_cast<const ulonglong2*>(Wm + u * 64);
                ull xa  = pack2(x0s[j]);
                ull xb0 = pack2(f1[3*j + 0]);
                ull xb1 = pack2(f1[3*j + 1]);
                ull xb2 = pack2(f1[3*j + 2]);
                #pragma unroll
                for (int p = 0; p < 4; p++) {         // w000 (x0)
                    ulonglong2 w = wp[p];
                    ffma2(z000[2*p],   xa, w.x);
                    ffma2(z000[2*p+1], xa, w.y);
                }
                #pragma unroll
                for (int p = 0; p < 4; p++) {         // w011 (x0)
                    ulonglong2 w = wp[4 + p];
                    ffma2(z011[2*p],   xa, w.x);
                    ffma2(z011[2*p+1], xa, w.y);
                }
                #pragma unroll
                for (int p = 0; p < 4; p++) {         // w110 (x1[.,i])
                    ulonglong2 w = wp[8 + p];
                    ffma2(z110[0][2*p],   xb0, w.x);
                    ffma2(z110[0][2*p+1], xb0, w.y);
                    ffma2(z110[1][2*p],   xb1, w.x);
                    ffma2(z110[1][2*p+1], xb1, w.y);
                    ffma2(z110[2][2*p],   xb2, w.x);
                    ffma2(z110[2][2*p+1], xb2, w.y);
                }
                #pragma unroll
                for (int p = 0; p < 4; p++) {         // w101 (x1[.,k])
                    ulonglong2 w = wp[12 + p];
                    ffma2(z101[0][2*p],   xb0, w.x);
                    ffma2(z101[0][2*p+1], xb0, w.y);
                    ffma2(z101[1][2*p],   xb1, w.x);
                    ffma2(z101[1][2*p+1], xb1, w.y);
                    ffma2(z101[2][2*p],   xb2, w.x);
                    ffma2(z101[2][2*p+1], xb2, w.y);
                }
            }
        }
        __syncwarp();   // all lanes done reading buffer before it is restaged
    }

    // ---------------- epilogue (registers only) ----------------
    const int node = nodeBase + lane;

    float f000[16], f011[16], f110[3][16], f101[3][16];
    #pragma unroll
    for (int p = 0; p < 8; p++) {
        unpack2(z000[p], f000[2*p], f000[2*p+1]);
        unpack2(z011[p], f011[2*p], f011[2*p+1]);
        #pragma unroll
        for (int i = 0; i < 3; i++) {
            unpack2(z110[i][p], f110[i][2*p], f110[i][2*p+1]);
            unpack2(z101[i][p], f101[i][2*p], f101[i][2*p+1]);
        }
    }

    float y[16];
    {
        const float4* p4 = reinterpret_cast<const float4*>(pf + (size_t)node * 16);
        #pragma unroll
        for (int q = 0; q < 4; q++) {
            float4 t = p4[q];
            y[4*q+0] = t.x; y[4*q+1] = t.y; y[4*q+2] = t.z; y[4*q+3] = t.w;
        }
    }

    float o0[4], o1[4][3];
    #pragma unroll
    for (int w = 0; w < 4; w++) {
        float s = 0.f, t = 0.f;
        #pragma unroll
        for (int v = 0; v < 4; v++) {
            s += f000[v*4 + w] * y[v];
            #pragma unroll
            for (int i = 0; i < 3; i++)
                t += f110[i][v*4 + w] * y[4 + 3*v + i];
        }
        o0[w] = s + t;
    }
    #pragma unroll
    for (int w = 0; w < 4; w++) {
        #pragma unroll
        for (int k = 0; k < 3; k++) {
            float s = 0.f, t = 0.f;
            #pragma unroll
            for (int v = 0; v < 4; v++) {
                s += f011[v*4 + w]    * y[4 + 3*v + k];
                t += f101[k][v*4 + w] * y[v];
            }
            o1[w][k] = s + t;
        }
    }
    o0[0] = 0.0f;   // reference zeroes out[:,0]

    float4* o4 = reinterpret_cast<float4*>(out + (size_t)node * 16);
    o4[0] = make_float4(o0[0],    o0[1],    o0[2],    o0[3]);
    o4[1] = make_float4(o1[0][0], o1[0][1], o1[0][2], o1[1][0]);
    o4[2] = make_float4(o1[1][1], o1[1][2], o1[2][0], o1[2][1]);
    o4[3] = make_float4(o1[2][2], o1[3][0], o1[3][1], o1[3][2]);
}

// naive tail kernel (only runs if n % 128 != 0; negligible work)
__global__ void fctp_tail(
    const float* __restrict__ nf, const float* __restrict__ pf,
    const float* __restrict__ w000, const float* __restrict__ w011,
    const float* __restrict__ w101, const float* __restrict__ w110,
    float* __restrict__ out, int start, int n)
{
    int node = start + blockIdx.x * blockDim.x + threadIdx.x;
    if (node >= n) return;
    const float* x = nf + (size_t)node * 512;
    const float* y = pf + (size_t)node * 16;
    float y0v[4], y1v[4][3];
    for (int v0 = 0; v0 < 4; v0++) {
        y0v[v0] = y[v0];
        for (int i = 0; i < 3; i++) y1v[v0][i] = y[4 + 3*v0 + i];
    }
    float o0[4] = {0,0,0,0}, o1[4][3] = {};
    for (int u = 0; u < 128; u++) {
        float x0u = x[u];
        float x1u[3] = { x[128 + 3*u], x[128 + 3*u + 1], x[128 + 3*u + 2] };
        for (int v0 = 0; v0 < 4; v0++) {
            float s110 = x1u[0]*y1v[v0][0] + x1u[1]*y1v[v0][1] + x1u[2]*y1v[v0][2];
            float xy0 = x0u * y0v[v0];
            for (int w = 0; w < 4; w++) {
                int idx = u*16 + v0*4 + w;
                o0[w] += 3.125e-4f * xy0 * w000[idx]
                       + 1.8042195912175807e-4f * s110 * w110[idx];
                for (int k = 0; k < 3; k++)
                    o1[w][k] += 3.125e-4f * (x0u * y1v[v0][k] * w011[idx]
                                           + x1u[k] * y0v[v0] * w101[idx]);
            }
        }
    }
    o0[0] = 0.0f;
    float* op = out + (size_t)node * 16;
    for (int w = 0; w < 4; w++) op[w] = o0[w];
    for (int w = 0; w < 4; w++)
        for (int k = 0; k < 3; k++) op[4 + 3*w + k] = o1[w][k];
}

extern "C" void kernel_launch(void* const* d_in, const int* in_sizes, int n_in,
                              void* d_out, int out_size) {
    const float* nf   = (const float*)d_in[0];
    const float* pf   = (const float*)d_in[1];
    const float* w000 = (const float*)d_in[2];
    const float* w011 = (const float*)d_in[3];
    const float* w101 = (const float*)d_in[4];
    const float* w110 = (const float*)d_in[5];
    float* out = (float*)d_out;
    int n = in_sizes[0] / 512;
    int nb  = n >> 7;
    int rem = n & 127;
    cudaFuncSetAttribute(fctp_main, cudaFuncAttributeMaxDynamicSharedMemorySize, SMEM_BYTES);
    if (nb > 0)
        fctp_main<<<nb, 128, SMEM_BYTES>>>(nf, pf, w000, w011, w101, w110, out);
    if (rem > 0)
        fctp_tail<<<1, 128>>>(nf, pf, w000, w011, w101, w110, out, nb * 128, n);
}